// round 6
// baseline (speedup 1.0000x reference)
#include <cuda_runtime.h>
#include <cuda_bf16.h>

// PairwiseMax: B=4096, D1=256, D2=256, F=128
// out[b, 0:256]   = x0[b,i] >= 0 ? x0[b,i]*max(x1[b,:]) : x0[b,i]*min(x1[b,:])
// out[b, 256:384] = x2[b,:]
//
// R6: two-phase split to break the 4096-warp concurrency cap.
//  K1: warp-per-row reduction of x1 -> g_mxmn[row] (4 MB read).
//  K2: thread-per-float4 streaming over the full output (12288 warps,
//      no shuffles/barriers): scale x0 by broadcast {mx,mn}, copy x2.
//  Branchless: mx>=mn  =>  o = fmaxf(c*mx, c*mn).

#define B_ROWS 4096

__device__ float2 g_mxmn[B_ROWS];

// ---------------- K1: per-row max/min of x1 ----------------
#define K1_WARPS 8
#define K1_THREADS (K1_WARPS * 32)
#define K1_BLOCKS (B_ROWS / K1_WARPS)   // 512

__global__ __launch_bounds__(K1_THREADS) void reduce_kernel(
    const float4* __restrict__ x1v)    // [B, 64] float4
{
    const int warp_id = threadIdx.x >> 5;
    const int lane    = threadIdx.x & 31;
    const int row     = blockIdx.x * K1_WARPS + warp_id;

    const float4* x1row = x1v + (size_t)row * 64;
    float4 a = x1row[lane];
    float4 b = x1row[lane + 32];

    float mx = fmaxf(fmaxf(fmaxf(a.x, a.y), fmaxf(a.z, a.w)),
                     fmaxf(fmaxf(b.x, b.y), fmaxf(b.z, b.w)));
    float mn = fminf(fminf(fminf(a.x, a.y), fminf(a.z, a.w)),
                     fminf(fminf(b.x, b.y), fminf(b.z, b.w)));

    #pragma unroll
    for (int off = 16; off > 0; off >>= 1) {
        mx = fmaxf(mx, __shfl_xor_sync(0xFFFFFFFFu, mx, off));
        mn = fminf(mn, __shfl_xor_sync(0xFFFFFFFFu, mn, off));
    }

    if (lane == 0) g_mxmn[row] = make_float2(mx, mn);
}

// ---------------- K2: streaming scale + copy ----------------
// grid = (512, 3), 256 threads. Each thread handles one output float4.
// blockIdx.y: 0 -> out cols [0,32) f4 from x0[0:32); 1 -> cols [32,64)
// from x0[32:64); 2 -> cols [64,96) from x2.
#define K2_THREADS 256
#define K2_BLOCKS_X ((B_ROWS * 32) / K2_THREADS)   // 512

__global__ __launch_bounds__(K2_THREADS) void stream_kernel(
    const float4* __restrict__ x0v,   // [B, 64] float4
    const float4* __restrict__ x2v,   // [B, 32] float4
    float4* __restrict__ outv)        // [B, 96] float4
{
    const int tid = blockIdx.x * K2_THREADS + threadIdx.x;  // 0..131071
    const int row = tid >> 5;    // 32 float4 per segment-row
    const int col = tid & 31;
    const int seg = blockIdx.y;

    if (seg == 2) {
        // x2 passthrough
        outv[(size_t)row * 96 + 64 + col] = x2v[(size_t)row * 32 + col];
    } else {
        // x0 scale: all lanes in a warp share `row` -> broadcast load
        const float2 mm = g_mxmn[row];            // mm.x = mx, mm.y = mn
        const float4 c  = x0v[(size_t)row * 64 + (seg << 5) + col];

        float4 o;
        o.x = fmaxf(c.x * mm.x, c.x * mm.y);
        o.y = fmaxf(c.y * mm.x, c.y * mm.y);
        o.z = fmaxf(c.z * mm.x, c.z * mm.y);
        o.w = fmaxf(c.w * mm.x, c.w * mm.y);

        outv[(size_t)row * 96 + (seg << 5) + col] = o;
    }
}

extern "C" void kernel_launch(void* const* d_in, const int* in_sizes, int n_in,
                              void* d_out, int out_size)
{
    const float4* x0v = (const float4*)d_in[0];
    const float4* x1v = (const float4*)d_in[1];
    const float4* x2v = (const float4*)d_in[2];
    float4* outv = (float4*)d_out;

    reduce_kernel<<<K1_BLOCKS, K1_THREADS>>>(x1v);

    dim3 grid2(K2_BLOCKS_X, 3);
    stream_kernel<<<grid2, K2_THREADS>>>(x0v, x2v, outv);
}

// round 7
// speedup vs baseline: 1.3196x; 1.3196x over previous
#include <cuda_runtime.h>
#include <cuda_bf16.h>

// PairwiseMax: B=4096, D1=256, D2=256, F=128
// out[b, 0:256]   = x0[b,i] >= 0 ? x0[b,i]*max(x1[b,:]) : x0[b,i]*min(x1[b,:])
// out[b, 256:384] = x2[b,:]
//
// R7: R5 geometry (1024 blocks x 128 thr, warp-per-row, best harness time)
// with the warp-internal critical path shortened:
//  - 10-SHFL butterfly -> 2x redux.sync.u32 (sm_80+ baseline) on the
//    monotone float<->ordered-uint map (~130cy -> ~30cy).
//  - branchless select: mx>=mn  =>  o = fmaxf(c*mx, c*mn).

#define B_ROWS 4096
#define WARPS_PER_BLOCK 4
#define THREADS (WARPS_PER_BLOCK * 32)           // 128
#define BLOCKS (B_ROWS / WARPS_PER_BLOCK)        // 1024

// Monotone map: float total order -> unsigned total order.
__device__ __forceinline__ unsigned enc_ord(float f) {
    unsigned u = __float_as_uint(f);
    return u ^ ((unsigned)((int)u >> 31) | 0x80000000u);
}
__device__ __forceinline__ float dec_ord(unsigned k) {
    return __uint_as_float(k ^ ((unsigned)(((int)~k) >> 31) | 0x80000000u));
}

__global__ __launch_bounds__(THREADS) void pairwise_max_kernel(
    const float4* __restrict__ x0v,   // [B, 64] float4
    const float4* __restrict__ x1v,   // [B, 64] float4
    const float4* __restrict__ x2v,   // [B, 32] float4
    float4* __restrict__ outv)        // [B, 96] float4
{
    const int warp_id = threadIdx.x >> 5;
    const int lane    = threadIdx.x & 31;
    const int row     = blockIdx.x * WARPS_PER_BLOCK + warp_id;  // exact 4096

    const float4* x1row  = x1v + (size_t)row * 64;
    const float4* x0row  = x0v + (size_t)row * 64;
    const float4* x2row  = x2v + (size_t)row * 32;
    float4*       outrow = outv + (size_t)row * 96;

    // Front-batch all 5 independent loads.
    float4 a = x1row[lane];
    float4 b = x1row[lane + 32];
    float4 c = x0row[lane];
    float4 d = x0row[lane + 32];
    float4 e = x2row[lane];

    float lmx = fmaxf(fmaxf(fmaxf(a.x, a.y), fmaxf(a.z, a.w)),
                      fmaxf(fmaxf(b.x, b.y), fmaxf(b.z, b.w)));
    float lmn = fminf(fminf(fminf(a.x, a.y), fminf(a.z, a.w)),
                      fminf(fminf(b.x, b.y), fminf(b.z, b.w)));

    // x2 passthrough store does not depend on the reduction — drain it early.
    outrow[lane + 64] = e;

    // Warp reduction via integer redux.sync on order-preserving keys.
    const float mx = dec_ord(__reduce_max_sync(0xFFFFFFFFu, enc_ord(lmx)));
    const float mn = dec_ord(__reduce_min_sync(0xFFFFFFFFu, enc_ord(lmn)));

    // Branchless: mx >= mn, so the selected product is the larger one.
    float4 oc, od;
    oc.x = fmaxf(c.x * mx, c.x * mn);
    oc.y = fmaxf(c.y * mx, c.y * mn);
    oc.z = fmaxf(c.z * mx, c.z * mn);
    oc.w = fmaxf(c.w * mx, c.w * mn);
    od.x = fmaxf(d.x * mx, d.x * mn);
    od.y = fmaxf(d.y * mx, d.y * mn);
    od.z = fmaxf(d.z * mx, d.z * mn);
    od.w = fmaxf(d.w * mx, d.w * mn);

    outrow[lane]      = oc;
    outrow[lane + 32] = od;
}

extern "C" void kernel_launch(void* const* d_in, const int* in_sizes, int n_in,
                              void* d_out, int out_size)
{
    const float4* x0v = (const float4*)d_in[0];
    const float4* x1v = (const float4*)d_in[1];
    const float4* x2v = (const float4*)d_in[2];
    float4* outv = (float4*)d_out;

    pairwise_max_kernel<<<BLOCKS, THREADS>>>(x0v, x1v, x2v, outv);
}